// round 16
// baseline (speedup 1.0000x reference)
#include <cuda_runtime.h>
#include <cuda_fp16.h>
#include <cstdint>

#define M_DIM 4096
#define K_DIM 2048
#define N_DIM 8192

#define BM 128
#define BN 128
#define BKH 64                      // halfs per k-tile (128 B per row)
#define STAGES 3
#define NT (K_DIM / BKH)            // 32 k-tiles
#define NTHREADS 128

#define A_CHUNKS (BM * 8)           // 1024 16B-chunks per A tile
#define B_CHUNKS (BN * 8)           // 1024
#define STAGE_BYTES ((A_CHUNKS + B_CHUNKS) * 16)   // 32768
#define MBAR_OFF   (STAGES * STAGE_BYTES)          // 98304
#define SMEM_TOTAL (MBAR_OFF + 64)

__constant__ float c_nf4[16] = {
    -1.0f, -0.6961928009986877f, -0.5250730514526367f, -0.39491748809814453f,
    -0.28444138169288635f, -0.18477343022823334f, -0.09105003625154495f, 0.0f,
    0.07958029955625534f, 0.16093020141124725f, 0.24611230194568634f,
    0.33791524171829224f, 0.44070982933044434f, 0.5626170039176941f,
    0.7229568362236023f, 1.0f
};

__device__ __align__(1024) __half g_W[(size_t)N_DIM * K_DIM];
__device__ __align__(1024) __half g_X[(size_t)M_DIM * K_DIM];

// ---------------------------------------------------------------------------
// Fused prep, 16 elems/thread (4 16B loads in flight), NF4 via SMEM table.
// Blocks [0,2048): convert x.  Blocks [2048,6144): dequant W.
// ---------------------------------------------------------------------------
__global__ void prep_kernel(const float* __restrict__ x,
                            const int* __restrict__ q,
                            const float* __restrict__ scale) {
    __shared__ float tbl[16];
    if (threadIdx.x < 16) tbl[threadIdx.x] = c_nf4[threadIdx.x];
    __syncthreads();

    if (blockIdx.x < 2048) {
        size_t i = ((size_t)blockIdx.x * blockDim.x + threadIdx.x) * 16;
        float4 f0 = *reinterpret_cast<const float4*>(x + i);
        float4 f1 = *reinterpret_cast<const float4*>(x + i + 4);
        float4 f2 = *reinterpret_cast<const float4*>(x + i + 8);
        float4 f3 = *reinterpret_cast<const float4*>(x + i + 12);
        __half2 h0 = __floats2half2_rn(f0.x, f0.y), h1 = __floats2half2_rn(f0.z, f0.w);
        __half2 h2 = __floats2half2_rn(f1.x, f1.y), h3 = __floats2half2_rn(f1.z, f1.w);
        __half2 h4 = __floats2half2_rn(f2.x, f2.y), h5 = __floats2half2_rn(f2.z, f2.w);
        __half2 h6 = __floats2half2_rn(f3.x, f3.y), h7 = __floats2half2_rn(f3.z, f3.w);
        uint4 v0 = { *(uint32_t*)&h0, *(uint32_t*)&h1, *(uint32_t*)&h2, *(uint32_t*)&h3 };
        uint4 v1 = { *(uint32_t*)&h4, *(uint32_t*)&h5, *(uint32_t*)&h6, *(uint32_t*)&h7 };
        *reinterpret_cast<uint4*>(g_X + i)     = v0;
        *reinterpret_cast<uint4*>(g_X + i + 8) = v1;
    } else {
        size_t i = ((size_t)(blockIdx.x - 2048) * blockDim.x + threadIdx.x) * 16;
        int4 c0 = *reinterpret_cast<const int4*>(q + i);
        int4 c1 = *reinterpret_cast<const int4*>(q + i + 4);
        int4 c2 = *reinterpret_cast<const int4*>(q + i + 8);
        int4 c3 = *reinterpret_cast<const int4*>(q + i + 12);
        float s = __ldg(scale + (i >> 6));   // 16 codes stay in one 64-block
        __half2 h0 = __floats2half2_rn(tbl[c0.x] * s, tbl[c0.y] * s);
        __half2 h1 = __floats2half2_rn(tbl[c0.z] * s, tbl[c0.w] * s);
        __half2 h2 = __floats2half2_rn(tbl[c1.x] * s, tbl[c1.y] * s);
        __half2 h3 = __floats2half2_rn(tbl[c1.z] * s, tbl[c1.w] * s);
        __half2 h4 = __floats2half2_rn(tbl[c2.x] * s, tbl[c2.y] * s);
        __half2 h5 = __floats2half2_rn(tbl[c2.z] * s, tbl[c2.w] * s);
        __half2 h6 = __floats2half2_rn(tbl[c3.x] * s, tbl[c3.y] * s);
        __half2 h7 = __floats2half2_rn(tbl[c3.z] * s, tbl[c3.w] * s);
        uint4 v0 = { *(uint32_t*)&h0, *(uint32_t*)&h1, *(uint32_t*)&h2, *(uint32_t*)&h3 };
        uint4 v1 = { *(uint32_t*)&h4, *(uint32_t*)&h5, *(uint32_t*)&h6, *(uint32_t*)&h7 };
        *reinterpret_cast<uint4*>(g_W + i)     = v0;
        *reinterpret_cast<uint4*>(g_W + i + 8) = v1;
    }
}

// ---------------------------------------------------------------------------
// GEMM: 128x128 CTA, 4 warps (64x64 warp tiles), 3-stage mbarrier ring,
// 2 CTAs/SM. Refill decoupled by one tile: during tile kt, refill tile kt+2
// into stage (kt-1)%3 — the empty-wait has a full tile of MMA slack.
// ---------------------------------------------------------------------------
__device__ __forceinline__ void cp_async16(uint32_t saddr, const void* gptr) {
    asm volatile("cp.async.cg.shared.global [%0], [%1], 16;\n" :: "r"(saddr), "l"(gptr));
}

__device__ __forceinline__ void ldsm_x4(uint32_t& r0, uint32_t& r1,
                                        uint32_t& r2, uint32_t& r3, uint32_t addr) {
    asm volatile("ldmatrix.sync.aligned.m8n8.x4.shared.b16 {%0,%1,%2,%3}, [%4];"
                 : "=r"(r0), "=r"(r1), "=r"(r2), "=r"(r3) : "r"(addr));
}

__device__ __forceinline__ void mma_f16(float* d, const uint32_t* a, const uint32_t* b) {
    asm volatile(
        "mma.sync.aligned.m16n8k16.row.col.f32.f16.f16.f32 "
        "{%0,%1,%2,%3}, {%4,%5,%6,%7}, {%8,%9}, {%0,%1,%2,%3};\n"
        : "+f"(d[0]), "+f"(d[1]), "+f"(d[2]), "+f"(d[3])
        : "r"(a[0]), "r"(a[1]), "r"(a[2]), "r"(a[3]), "r"(b[0]), "r"(b[1]));
}

#define MBAR_INIT(a, n) \
    asm volatile("mbarrier.init.shared.b64 [%0], %1;" :: "r"(a), "r"(n) : "memory")
#define MBAR_ARRIVE(a) \
    asm volatile("mbarrier.arrive.shared.b64 _, [%0];" :: "r"(a) : "memory")
#define CP_MBAR_ARRIVE(a) \
    asm volatile("cp.async.mbarrier.arrive.noinc.shared.b64 [%0];" :: "r"(a) : "memory")
#define MBAR_WAIT(a, ph) do {                                               \
    asm volatile("{\n\t.reg .pred P1;\n\t"                                  \
        "WL_%=:\n\t"                                                        \
        "mbarrier.try_wait.parity.acquire.cta.shared::cta.b64 P1, [%0], %1;\n\t" \
        "@P1 bra.uni WD_%=;\n\t"                                            \
        "bra.uni WL_%=;\n\t"                                                \
        "WD_%=:\n\t}" :: "r"(a), "r"((uint32_t)(ph)) : "memory");           \
} while (0)

__global__ __launch_bounds__(NTHREADS, 2)
void gemm_f16_kernel(const float* __restrict__ bias, float* __restrict__ out) {
    extern __shared__ char smem[];
    const uint32_t sb = (uint32_t)__cvta_generic_to_shared(smem);
    const uint32_t mb = sb + MBAR_OFF;   // full[s]=mb+s*16, empty[s]=mb+s*16+8

    const int tid  = threadIdx.x;
    const int lane = tid & 31;
    const int warp = tid >> 5;
    const int gid  = lane >> 2;
    const int tig  = lane & 3;
    const int wm   = (warp >> 1) * 64;
    const int wn   = (warp & 1) * 64;
    const int bm   = blockIdx.y * BM;
    const int bn   = blockIdx.x * BN;

    const __half* gA = g_X + (size_t)bm * K_DIM;
    const __half* gB = g_W + (size_t)bn * K_DIM;

    auto load_tile = [&](int s, int kt) {
        const uint32_t sba = sb + s * STAGE_BYTES;
        const int koff = kt * BKH;
        #pragma unroll
        for (int it = 0; it < 8; it++) {
            int idx = tid + it * NTHREADS;
            int r = idx >> 3, c = idx & 7;
            cp_async16(sba + (r * 8 + ((r & 7) ^ c)) * 16,
                       gA + (size_t)r * K_DIM + koff + c * 8);
        }
        const uint32_t sbb = sba + A_CHUNKS * 16;
        #pragma unroll
        for (int it = 0; it < 8; it++) {
            int idx = tid + it * NTHREADS;
            int r = idx >> 3, c = idx & 7;
            cp_async16(sbb + (r * 8 + ((r & 7) ^ c)) * 16,
                       gB + (size_t)r * K_DIM + koff + c * 8);
        }
    };

    float acc[4][8][4];
    #pragma unroll
    for (int mi = 0; mi < 4; mi++)
        #pragma unroll
        for (int ni = 0; ni < 8; ni++)
            #pragma unroll
            for (int r = 0; r < 4; r++)
                acc[mi][ni][r] = 0.0f;

    const int a_row_off = lane & 15;
    const int a_hi      = lane >> 4;
    const int b_row_off = (lane & 7) + ((lane >> 4) << 3);
    const int b_hi      = (lane >> 3) & 1;

    auto do_slice = [&](uint32_t sA, uint32_t sB, int ks) {
        const int c0 = 2 * ks;
        uint32_t a[4][4], b[4][4];
        #pragma unroll
        for (int mi = 0; mi < 4; mi++) {
            const int row = wm + mi * 16 + a_row_off;
            const uint32_t addr = sA + (row * 8 + ((row & 7) ^ (c0 + a_hi))) * 16;
            ldsm_x4(a[mi][0], a[mi][1], a[mi][2], a[mi][3], addr);
        }
        #pragma unroll
        for (int p = 0; p < 4; p++) {
            const int row = wn + p * 16 + b_row_off;
            const uint32_t addr = sB + (row * 8 + ((row & 7) ^ (c0 + b_hi))) * 16;
            ldsm_x4(b[p][0], b[p][1], b[p][2], b[p][3], addr);
        }
        #pragma unroll
        for (int mi = 0; mi < 4; mi++)
            #pragma unroll
            for (int p = 0; p < 4; p++) {
                mma_f16(acc[mi][2 * p],     a[mi], &b[p][0]);
                mma_f16(acc[mi][2 * p + 1], a[mi], &b[p][2]);
            }
    };

    // ---- init mbarriers ----
    if (tid == 0) {
        #pragma unroll
        for (int s = 0; s < STAGES; s++) {
            MBAR_INIT(mb + s * 16,     NTHREADS);   // full
            MBAR_INIT(mb + s * 16 + 8, NTHREADS);   // empty
        }
    }
    __syncthreads();

    // ---- prologue: fill stages 0..2 with tiles 0..2 ----
    load_tile(0, 0); CP_MBAR_ARRIVE(mb + 0 * 16);
    load_tile(1, 1); CP_MBAR_ARRIVE(mb + 1 * 16);
    load_tile(2, 2); CP_MBAR_ARRIVE(mb + 2 * 16);

    int phF0 = 0, phF1 = 0, phF2 = 0;     // full-wait phase per stage
    int phE0 = 0, phE1 = 0, phE2 = 0;     // empty-wait phase per stage

    // body: consume tile kt from stage s; refill tile kt+2 into stage
    // sp = (kt-1)%3 = (s+2)%3, guarded by kt in [1, NT-3].
    auto body = [&](int kt, int s, int& phF, int& phE_sp) {
        const uint32_t full  = mb + s * 16;
        const uint32_t sA = sb + s * STAGE_BYTES;
        const uint32_t sB = sA + A_CHUNKS * 16;
        const int sp = (s + 2) % 3;

        MBAR_WAIT(full, phF); phF ^= 1;
        do_slice(sA, sB, 0);

        if (kt >= 1 && kt + 2 < NT) {
            MBAR_WAIT(mb + sp * 16 + 8, phE_sp); phE_sp ^= 1;  // stage sp drained (tile kt-1)
            load_tile(sp, kt + 2);
            CP_MBAR_ARRIVE(mb + sp * 16);
        }

        do_slice(sA, sB, 1);
        do_slice(sA, sB, 2);
        do_slice(sA, sB, 3);
        MBAR_ARRIVE(full + 8);            // this thread done reading stage s
    };

    #pragma unroll 1
    for (int kt = 0; kt < 30; kt += 3) {  // NT = 32
        body(kt,     0, phF0, phE2);
        body(kt + 1, 1, phF1, phE0);
        body(kt + 2, 2, phF2, phE1);
    }
    body(30, 0, phF0, phE2);
    body(31, 1, phF1, phE0);

    // ---- epilogue ----
    #pragma unroll
    for (int mi = 0; mi < 4; mi++) {
        const int m = bm + wm + mi * 16 + gid;
        #pragma unroll
        for (int ni = 0; ni < 8; ni++) {
            const int n = bn + wn + ni * 8 + tig * 2;
            float2 bv = *reinterpret_cast<const float2*>(bias + n);
            float2 v0 = { acc[mi][ni][0] + bv.x, acc[mi][ni][1] + bv.y };
            float2 v1 = { acc[mi][ni][2] + bv.x, acc[mi][ni][3] + bv.y };
            *reinterpret_cast<float2*>(out + (size_t)m * N_DIM + n)       = v0;
            *reinterpret_cast<float2*>(out + (size_t)(m + 8) * N_DIM + n) = v1;
        }
    }
}

// ---------------------------------------------------------------------------
// Launch
// ---------------------------------------------------------------------------
extern "C" void kernel_launch(void* const* d_in, const int* in_sizes, int n_in,
                              void* d_out, int out_size) {
    const float* x     = (const float*)d_in[0];
    const int*   q     = (const int*)d_in[1];
    const float* scale = (const float*)d_in[2];
    const float* bias  = (const float*)d_in[3];
    float*       out   = (float*)d_out;

    prep_kernel<<<6144, 256>>>(x, q, scale);

    cudaFuncSetAttribute(gemm_f16_kernel,
                         cudaFuncAttributeMaxDynamicSharedMemorySize, SMEM_TOTAL);
    dim3 grid(N_DIM / BN, M_DIM / BM);   // (64, 32)
    gemm_f16_kernel<<<grid, NTHREADS, SMEM_TOTAL>>>(bias, out);
}

// round 17
// speedup vs baseline: 1.0047x; 1.0047x over previous
#include <cuda_runtime.h>
#include <cuda_fp16.h>
#include <cstdint>

#define M_DIM 4096
#define K_DIM 2048
#define N_DIM 8192

#define BM 128
#define BN 128
#define BKH 64                      // halfs per k-tile (128 B per row)
#define STAGES 3
#define NT (K_DIM / BKH)            // 32 k-tiles
#define NTHREADS 128

#define A_CHUNKS (BM * 8)           // 1024 16B-chunks per A tile
#define B_CHUNKS (BN * 8)           // 1024
#define STAGE_BYTES ((A_CHUNKS + B_CHUNKS) * 16)   // 32768
#define MBAR_OFF   (STAGES * STAGE_BYTES)          // 98304
#define SMEM_TOTAL (MBAR_OFF + 64)

__constant__ float c_nf4[16] = {
    -1.0f, -0.6961928009986877f, -0.5250730514526367f, -0.39491748809814453f,
    -0.28444138169288635f, -0.18477343022823334f, -0.09105003625154495f, 0.0f,
    0.07958029955625534f, 0.16093020141124725f, 0.24611230194568634f,
    0.33791524171829224f, 0.44070982933044434f, 0.5626170039176941f,
    0.7229568362236023f, 1.0f
};

__device__ __align__(1024) __half g_W[(size_t)N_DIM * K_DIM];
__device__ __align__(1024) __half g_X[(size_t)M_DIM * K_DIM];

// ---------------------------------------------------------------------------
// Fused prep, 16 elems/thread (4 16B loads in flight), NF4 via SMEM table.
// Blocks [0,2048): convert x.  Blocks [2048,6144): dequant W.   (R16 version)
// ---------------------------------------------------------------------------
__global__ void prep_kernel(const float* __restrict__ x,
                            const int* __restrict__ q,
                            const float* __restrict__ scale) {
    __shared__ float tbl[16];
    if (threadIdx.x < 16) tbl[threadIdx.x] = c_nf4[threadIdx.x];
    __syncthreads();

    if (blockIdx.x < 2048) {
        size_t i = ((size_t)blockIdx.x * blockDim.x + threadIdx.x) * 16;
        float4 f0 = *reinterpret_cast<const float4*>(x + i);
        float4 f1 = *reinterpret_cast<const float4*>(x + i + 4);
        float4 f2 = *reinterpret_cast<const float4*>(x + i + 8);
        float4 f3 = *reinterpret_cast<const float4*>(x + i + 12);
        __half2 h0 = __floats2half2_rn(f0.x, f0.y), h1 = __floats2half2_rn(f0.z, f0.w);
        __half2 h2 = __floats2half2_rn(f1.x, f1.y), h3 = __floats2half2_rn(f1.z, f1.w);
        __half2 h4 = __floats2half2_rn(f2.x, f2.y), h5 = __floats2half2_rn(f2.z, f2.w);
        __half2 h6 = __floats2half2_rn(f3.x, f3.y), h7 = __floats2half2_rn(f3.z, f3.w);
        uint4 v0 = { *(uint32_t*)&h0, *(uint32_t*)&h1, *(uint32_t*)&h2, *(uint32_t*)&h3 };
        uint4 v1 = { *(uint32_t*)&h4, *(uint32_t*)&h5, *(uint32_t*)&h6, *(uint32_t*)&h7 };
        *reinterpret_cast<uint4*>(g_X + i)     = v0;
        *reinterpret_cast<uint4*>(g_X + i + 8) = v1;
    } else {
        size_t i = ((size_t)(blockIdx.x - 2048) * blockDim.x + threadIdx.x) * 16;
        int4 c0 = *reinterpret_cast<const int4*>(q + i);
        int4 c1 = *reinterpret_cast<const int4*>(q + i + 4);
        int4 c2 = *reinterpret_cast<const int4*>(q + i + 8);
        int4 c3 = *reinterpret_cast<const int4*>(q + i + 12);
        float s = __ldg(scale + (i >> 6));   // 16 codes stay in one 64-block
        __half2 h0 = __floats2half2_rn(tbl[c0.x] * s, tbl[c0.y] * s);
        __half2 h1 = __floats2half2_rn(tbl[c0.z] * s, tbl[c0.w] * s);
        __half2 h2 = __floats2half2_rn(tbl[c1.x] * s, tbl[c1.y] * s);
        __half2 h3 = __floats2half2_rn(tbl[c1.z] * s, tbl[c1.w] * s);
        __half2 h4 = __floats2half2_rn(tbl[c2.x] * s, tbl[c2.y] * s);
        __half2 h5 = __floats2half2_rn(tbl[c2.z] * s, tbl[c2.w] * s);
        __half2 h6 = __floats2half2_rn(tbl[c3.x] * s, tbl[c3.y] * s);
        __half2 h7 = __floats2half2_rn(tbl[c3.z] * s, tbl[c3.w] * s);
        uint4 v0 = { *(uint32_t*)&h0, *(uint32_t*)&h1, *(uint32_t*)&h2, *(uint32_t*)&h3 };
        uint4 v1 = { *(uint32_t*)&h4, *(uint32_t*)&h5, *(uint32_t*)&h6, *(uint32_t*)&h7 };
        *reinterpret_cast<uint4*>(g_W + i)     = v0;
        *reinterpret_cast<uint4*>(g_W + i + 8) = v1;
    }
}

// ---------------------------------------------------------------------------
// GEMM: exact R15 structure (measured 304 us): 128x128 CTA, 4 warps (64x64
// warp tiles), 3-stage mbarrier ring, consume-then-refill in same body,
// 2 CTAs/SM. No block-wide __syncthreads in the main loop.
// ---------------------------------------------------------------------------
__device__ __forceinline__ void cp_async16(uint32_t saddr, const void* gptr) {
    asm volatile("cp.async.cg.shared.global [%0], [%1], 16;\n" :: "r"(saddr), "l"(gptr));
}

__device__ __forceinline__ void ldsm_x4(uint32_t& r0, uint32_t& r1,
                                        uint32_t& r2, uint32_t& r3, uint32_t addr) {
    asm volatile("ldmatrix.sync.aligned.m8n8.x4.shared.b16 {%0,%1,%2,%3}, [%4];"
                 : "=r"(r0), "=r"(r1), "=r"(r2), "=r"(r3) : "r"(addr));
}

__device__ __forceinline__ void mma_f16(float* d, const uint32_t* a, const uint32_t* b) {
    asm volatile(
        "mma.sync.aligned.m16n8k16.row.col.f32.f16.f16.f32 "
        "{%0,%1,%2,%3}, {%4,%5,%6,%7}, {%8,%9}, {%0,%1,%2,%3};\n"
        : "+f"(d[0]), "+f"(d[1]), "+f"(d[2]), "+f"(d[3])
        : "r"(a[0]), "r"(a[1]), "r"(a[2]), "r"(a[3]), "r"(b[0]), "r"(b[1]));
}

#define MBAR_INIT(a, n) \
    asm volatile("mbarrier.init.shared.b64 [%0], %1;" :: "r"(a), "r"(n) : "memory")
#define MBAR_ARRIVE(a) \
    asm volatile("mbarrier.arrive.shared.b64 _, [%0];" :: "r"(a) : "memory")
#define CP_MBAR_ARRIVE(a) \
    asm volatile("cp.async.mbarrier.arrive.noinc.shared.b64 [%0];" :: "r"(a) : "memory")
#define MBAR_WAIT(a, ph) do {                                               \
    asm volatile("{\n\t.reg .pred P1;\n\t"                                  \
        "WL_%=:\n\t"                                                        \
        "mbarrier.try_wait.parity.acquire.cta.shared::cta.b64 P1, [%0], %1;\n\t" \
        "@P1 bra.uni WD_%=;\n\t"                                            \
        "bra.uni WL_%=;\n\t"                                                \
        "WD_%=:\n\t}" :: "r"(a), "r"((uint32_t)(ph)) : "memory");           \
} while (0)

__global__ __launch_bounds__(NTHREADS, 2)
void gemm_f16_kernel(const float* __restrict__ bias, float* __restrict__ out) {
    extern __shared__ char smem[];
    const uint32_t sb = (uint32_t)__cvta_generic_to_shared(smem);
    const uint32_t mb = sb + MBAR_OFF;   // full[s]=mb+s*16, empty[s]=mb+s*16+8

    const int tid  = threadIdx.x;
    const int lane = tid & 31;
    const int warp = tid >> 5;           // 0..3
    const int gid  = lane >> 2;
    const int tig  = lane & 3;
    const int wm   = (warp >> 1) * 64;
    const int wn   = (warp & 1) * 64;
    const int bm   = blockIdx.y * BM;
    const int bn   = blockIdx.x * BN;

    const __half* gA = g_X + (size_t)bm * K_DIM;
    const __half* gB = g_W + (size_t)bn * K_DIM;

    auto load_tile = [&](int s, int kt) {
        const uint32_t sba = sb + s * STAGE_BYTES;
        const int koff = kt * BKH;
        #pragma unroll
        for (int it = 0; it < 8; it++) {
            int idx = tid + it * NTHREADS;
            int r = idx >> 3, c = idx & 7;
            cp_async16(sba + (r * 8 + ((r & 7) ^ c)) * 16,
                       gA + (size_t)r * K_DIM + koff + c * 8);
        }
        const uint32_t sbb = sba + A_CHUNKS * 16;
        #pragma unroll
        for (int it = 0; it < 8; it++) {
            int idx = tid + it * NTHREADS;
            int r = idx >> 3, c = idx & 7;
            cp_async16(sbb + (r * 8 + ((r & 7) ^ c)) * 16,
                       gB + (size_t)r * K_DIM + koff + c * 8);
        }
    };

    float acc[4][8][4];
    #pragma unroll
    for (int mi = 0; mi < 4; mi++)
        #pragma unroll
        for (int ni = 0; ni < 8; ni++)
            #pragma unroll
            for (int r = 0; r < 4; r++)
                acc[mi][ni][r] = 0.0f;

    const int a_row_off = lane & 15;
    const int a_hi      = lane >> 4;
    const int b_row_off = (lane & 7) + ((lane >> 4) << 3);
    const int b_hi      = (lane >> 3) & 1;

    auto do_slice = [&](uint32_t sA, uint32_t sB, int ks) {
        const int c0 = 2 * ks;
        uint32_t a[4][4], b[4][4];
        #pragma unroll
        for (int mi = 0; mi < 4; mi++) {
            const int row = wm + mi * 16 + a_row_off;
            const uint32_t addr = sA + (row * 8 + ((row & 7) ^ (c0 + a_hi))) * 16;
            ldsm_x4(a[mi][0], a[mi][1], a[mi][2], a[mi][3], addr);
        }
        #pragma unroll
        for (int p = 0; p < 4; p++) {
            const int row = wn + p * 16 + b_row_off;
            const uint32_t addr = sB + (row * 8 + ((row & 7) ^ (c0 + b_hi))) * 16;
            ldsm_x4(b[p][0], b[p][1], b[p][2], b[p][3], addr);
        }
        #pragma unroll
        for (int mi = 0; mi < 4; mi++)
            #pragma unroll
            for (int p = 0; p < 4; p++) {
                mma_f16(acc[mi][2 * p],     a[mi], &b[p][0]);
                mma_f16(acc[mi][2 * p + 1], a[mi], &b[p][2]);
            }
    };

    // ---- init mbarriers ----
    if (tid == 0) {
        #pragma unroll
        for (int s = 0; s < STAGES; s++) {
            MBAR_INIT(mb + s * 16,     NTHREADS);   // full: 128 cp-arrive.noinc
            MBAR_INIT(mb + s * 16 + 8, NTHREADS);   // empty: 128 thread arrivals
        }
    }
    __syncthreads();

    // ---- prologue: fill all 3 stages (tiles 0,1,2) ----
    load_tile(0, 0); CP_MBAR_ARRIVE(mb + 0 * 16);
    load_tile(1, 1); CP_MBAR_ARRIVE(mb + 1 * 16);
    load_tile(2, 2); CP_MBAR_ARRIVE(mb + 2 * 16);

    // ---- main loop: per-thread phase per stage, no block barrier ----
    int ph0 = 0, ph1 = 0, ph2 = 0;

    auto body = [&](int kt, int s, int& ph) {
        const uint32_t full  = mb + s * 16;
        const uint32_t empty = full + 8;
        const uint32_t sA = sb + s * STAGE_BYTES;
        const uint32_t sB = sA + A_CHUNKS * 16;

        MBAR_WAIT(full, ph);                 // tile kt data ready
        do_slice(sA, sB, 0);
        do_slice(sA, sB, 1);
        do_slice(sA, sB, 2);
        do_slice(sA, sB, 3);
        MBAR_ARRIVE(empty);                  // this thread done reading stage s

        if (kt + 3 < NT) {
            MBAR_WAIT(empty, ph);            // all threads done with this use
            load_tile(s, kt + 3);
            CP_MBAR_ARRIVE(full);
        }
        ph ^= 1;
    };

    #pragma unroll 1
    for (int kt = 0; kt < 30; kt += 3) {     // NT = 32 = 3*10 + 2
        body(kt,     0, ph0);
        body(kt + 1, 1, ph1);
        body(kt + 2, 2, ph2);
    }
    body(30, 0, ph0);
    body(31, 1, ph1);

    // ---- epilogue ----
    #pragma unroll
    for (int mi = 0; mi < 4; mi++) {
        const int m = bm + wm + mi * 16 + gid;
        #pragma unroll
        for (int ni = 0; ni < 8; ni++) {
            const int n = bn + wn + ni * 8 + tig * 2;
            float2 bv = *reinterpret_cast<const float2*>(bias + n);
            float2 v0 = { acc[mi][ni][0] + bv.x, acc[mi][ni][1] + bv.y };
            float2 v1 = { acc[mi][ni][2] + bv.x, acc[mi][ni][3] + bv.y };
            *reinterpret_cast<float2*>(out + (size_t)m * N_DIM + n)       = v0;
            *reinterpret_cast<float2*>(out + (size_t)(m + 8) * N_DIM + n) = v1;
        }
    }
}

// ---------------------------------------------------------------------------
// Launch
// ---------------------------------------------------------------------------
extern "C" void kernel_launch(void* const* d_in, const int* in_sizes, int n_in,
                              void* d_out, int out_size) {
    const float* x     = (const float*)d_in[0];
    const int*   q     = (const int*)d_in[1];
    const float* scale = (const float*)d_in[2];
    const float* bias  = (const float*)d_in[3];
    float*       out   = (float*)d_out;

    prep_kernel<<<6144, 256>>>(x, q, scale);

    cudaFuncSetAttribute(gemm_f16_kernel,
                         cudaFuncAttributeMaxDynamicSharedMemorySize, SMEM_TOTAL);
    dim3 grid(N_DIM / BN, M_DIM / BM);   // (64, 32)
    gemm_f16_kernel<<<grid, NTHREADS, SMEM_TOTAL>>>(bias, out);
}